// round 1
// baseline (speedup 1.0000x reference)
#include <cuda_runtime.h>
#include <math.h>

#define DM   768
#define DI   1536
#define DS   16
#define DTR  48
#define NL   4
#define VOC  32000
#define BB   2
#define LL   1024
#define BL   (BB*LL)      // 2048
#define XDW  (DTR + 2*DS) // 80

// ---------------- scratch (device globals; no allocation allowed) ----------
__device__ float g_x   [BL*DM];
__device__ float g_xn  [BL*DM];
__device__ float g_xr  [BL*2*DI];
__device__ float g_xin [BL*DI];
__device__ float g_xdbl[BL*XDW];
__device__ float g_delta[BL*DI];
__device__ float g_y   [BL*DI];

// ---------------- embedding lookup ----------------
__global__ void embed_kernel(const int* __restrict__ ids,
                             const float* __restrict__ emb,
                             float* __restrict__ x) {
    int i = blockIdx.x * blockDim.x + threadIdx.x;
    if (i >= BL * DM) return;
    int r = i / DM, c = i % DM;
    x[i] = emb[(size_t)ids[r] * DM + c];
}

// ---------------- rmsnorm (one block per row of 768) ----------------
__global__ __launch_bounds__(256) void rmsnorm_kernel(const float* __restrict__ x,
                                                      const float* __restrict__ w,
                                                      float* __restrict__ o) {
    int row = blockIdx.x;
    const float* xrow = x + (size_t)row * DM;
    float s = 0.f;
    for (int c = threadIdx.x; c < DM; c += 256) { float v = xrow[c]; s = fmaf(v, v, s); }
    #pragma unroll
    for (int off = 16; off; off >>= 1) s += __shfl_xor_sync(0xffffffffu, s, off);
    __shared__ float red[8];
    if ((threadIdx.x & 31) == 0) red[threadIdx.x >> 5] = s;
    __syncthreads();
    float tot = red[0] + red[1] + red[2] + red[3] + red[4] + red[5] + red[6] + red[7];
    float sc = rsqrtf(tot * (1.0f / DM) + 1e-5f);
    for (int c = threadIdx.x; c < DM; c += 256)
        o[(size_t)row * DM + c] = xrow[c] * sc * w[c];
}

// ---------------- tiled fp32 GEMM:  C(MxN) = A(MxK) * B(NxK)^T  ----------------
// A row-major lda, B row-major ldb (weights stored (out,in)), C row-major ldc.
// BM=BN=128, BK=16, 256 threads, 8x8 per thread. K must be multiple of 16,
// M multiple of 128. N is guarded.
template<bool ADD>
__global__ __launch_bounds__(256) void gemm_nt(const float* __restrict__ A, int lda,
                                               const float* __restrict__ B, int ldb,
                                               float* __restrict__ C, int ldc,
                                               int M, int N, int K) {
    const int BM = 128, BN = 128, BK = 16;
    __shared__ float As[BK][BM];
    __shared__ float Bs[BK][BN + 4];

    int m0 = blockIdx.y * BM;
    int n0 = blockIdx.x * BN;
    int tid = threadIdx.x;

    int arow = tid >> 2;          // 0..63
    int acol = (tid & 3) << 2;    // 0,4,8,12
    int ty = tid >> 4;            // 0..15
    int tx = tid & 15;            // 0..15

    float acc[8][8];
    #pragma unroll
    for (int i = 0; i < 8; i++)
        #pragma unroll
        for (int j = 0; j < 8; j++) acc[i][j] = 0.f;

    for (int k0 = 0; k0 < K; k0 += BK) {
        #pragma unroll
        for (int r = 0; r < 2; ++r) {
            int row = arow + r * 64;
            float4 v = *(const float4*)(A + (size_t)(m0 + row) * lda + k0 + acol);
            As[acol + 0][row] = v.x;
            As[acol + 1][row] = v.y;
            As[acol + 2][row] = v.z;
            As[acol + 3][row] = v.w;
        }
        #pragma unroll
        for (int r = 0; r < 2; ++r) {
            int row = arow + r * 64;
            float4 v = make_float4(0.f, 0.f, 0.f, 0.f);
            if (n0 + row < N)
                v = *(const float4*)(B + (size_t)(n0 + row) * ldb + k0 + acol);
            Bs[acol + 0][row] = v.x;
            Bs[acol + 1][row] = v.y;
            Bs[acol + 2][row] = v.z;
            Bs[acol + 3][row] = v.w;
        }
        __syncthreads();
        #pragma unroll
        for (int k = 0; k < BK; ++k) {
            float a[8], b[8];
            *(float4*)&a[0] = *(const float4*)&As[k][ty * 8];
            *(float4*)&a[4] = *(const float4*)&As[k][ty * 8 + 4];
            *(float4*)&b[0] = *(const float4*)&Bs[k][tx * 8];
            *(float4*)&b[4] = *(const float4*)&Bs[k][tx * 8 + 4];
            #pragma unroll
            for (int i = 0; i < 8; i++)
                #pragma unroll
                for (int j = 0; j < 8; j++)
                    acc[i][j] = fmaf(a[i], b[j], acc[i][j]);
        }
        __syncthreads();
    }

    #pragma unroll
    for (int i = 0; i < 8; i++) {
        int m = m0 + ty * 8 + i;
        #pragma unroll
        for (int j = 0; j < 8; j += 4) {
            int n = n0 + tx * 8 + j;
            if (n < N) {
                float* Cp = C + (size_t)m * ldc + n;
                float4 v;
                v.x = acc[i][j + 0]; v.y = acc[i][j + 1];
                v.z = acc[i][j + 2]; v.w = acc[i][j + 3];
                if (ADD) {
                    float4 o = *(const float4*)Cp;
                    v.x += o.x; v.y += o.y; v.z += o.z; v.w += o.w;
                }
                *(float4*)Cp = v;
            }
        }
    }
}

// ---------------- causal depthwise conv (D_CONV=4) + SiLU ----------------
__global__ void conv_silu_kernel(const float* __restrict__ xr,
                                 const float* __restrict__ cw,
                                 const float* __restrict__ cb,
                                 float* __restrict__ xin) {
    int i = blockIdx.x * blockDim.x + threadIdx.x;
    if (i >= BL * DI) return;
    int d = i % DI;
    int bl = i / DI;
    int l = bl % LL;
    float w0 = cw[d * 4 + 0], w1 = cw[d * 4 + 1], w2 = cw[d * 4 + 2], w3 = cw[d * 4 + 3];
    const float* base = xr + (size_t)bl * (2 * DI) + d;
    float acc = cb[d];
    if (l >= 3) acc = fmaf(w0, base[-3 * (2 * DI)], acc);
    if (l >= 2) acc = fmaf(w1, base[-2 * (2 * DI)], acc);
    if (l >= 1) acc = fmaf(w2, base[-1 * (2 * DI)], acc);
    acc = fmaf(w3, base[0], acc);
    xin[i] = acc / (1.f + expf(-acc));   // silu
}

// ---------------- dt bias + softplus (in-place on delta) ----------------
__global__ void dt_act_kernel(float* __restrict__ delta, const float* __restrict__ b) {
    int i = blockIdx.x * blockDim.x + threadIdx.x;
    if (i >= BL * DI) return;
    int d = i % DI;
    float v = delta[i] + b[d];
    delta[i] = (v > 0.f) ? v + log1pf(expf(-v)) : log1pf(expf(v));
}

// ---------------- selective scan ----------------
// One thread per (b, d, half): handles 8 of the 16 states in registers,
// pairwise shfl-reduce for y. Software-pipelined loads.
__global__ __launch_bounds__(128) void scan_kernel(const float* __restrict__ u,
                                                   const float* __restrict__ delta,
                                                   const float* __restrict__ xdbl,
                                                   const float* __restrict__ A_log,
                                                   const float* __restrict__ Dp,
                                                   float* __restrict__ y) {
    int tid = blockIdx.x * blockDim.x + threadIdx.x;
    if (tid >= BB * DI * 2) return;
    int half = tid & 1;
    int pair = tid >> 1;
    int d = pair % DI;
    int b = pair / DI;

    float A[8];
    float A0 = -expf(A_log[d * DS]);
    bool structured = true;
    #pragma unroll
    for (int n = 0; n < 8; n++) {
        int ng = half * 8 + n;
        A[n] = -expf(A_log[d * DS + ng]);
        float e = (float)(ng + 1) * A0;
        if (fabsf(A[n] - e) > 1e-3f * fabsf(e)) structured = false;
    }
    float Dd = Dp[d];
    float h[8];
    #pragma unroll
    for (int n = 0; n < 8; n++) h[n] = 0.f;

    const float* up = u + (size_t)b * LL * DI + d;
    const float* dp = delta + (size_t)b * LL * DI + d;
    const float* xp = xdbl + (size_t)b * LL * XDW + DTR + half * 8;
    float* yp = y + (size_t)b * LL * DI + d;

    float del = dp[0], uu = up[0];
    float4 B0 = *(const float4*)(xp);
    float4 B1 = *(const float4*)(xp + 4);
    float4 C0 = *(const float4*)(xp + 16);
    float4 C1 = *(const float4*)(xp + 20);

    for (int l = 0; l < LL; ++l) {
        float ndel = 0.f, nuu = 0.f;
        float4 nB0 = B0, nB1 = B1, nC0 = C0, nC1 = C1;
        if (l + 1 < LL) {
            ndel = dp[(size_t)(l + 1) * DI];
            nuu  = up[(size_t)(l + 1) * DI];
            const float* nx = xp + (size_t)(l + 1) * XDW;
            nB0 = *(const float4*)(nx);
            nB1 = *(const float4*)(nx + 4);
            nC0 = *(const float4*)(nx + 16);
            nC1 = *(const float4*)(nx + 20);
        }
        float Ba[8] = {B0.x, B0.y, B0.z, B0.w, B1.x, B1.y, B1.z, B1.w};
        float Ca[8] = {C0.x, C0.y, C0.z, C0.w, C1.x, C1.y, C1.z, C1.w};
        float dbu = del * uu;
        float ys = 0.f;
        if (structured) {
            float t = __expf(A0 * del);
            float p;
            if (half == 0) p = t;
            else { float t2 = t * t, t4 = t2 * t2, t8 = t4 * t4; p = t8 * t; }
            #pragma unroll
            for (int n = 0; n < 8; n++) {
                h[n] = fmaf(p, h[n], dbu * Ba[n]);
                ys = fmaf(h[n], Ca[n], ys);
                p *= t;
            }
        } else {
            #pragma unroll
            for (int n = 0; n < 8; n++) {
                float dA = __expf(A[n] * del);
                h[n] = fmaf(dA, h[n], dbu * Ba[n]);
                ys = fmaf(h[n], Ca[n], ys);
            }
        }
        ys += __shfl_xor_sync(0xffffffffu, ys, 1);
        if (half == 0) yp[(size_t)l * DI] = fmaf(uu, Dd, ys);
        del = ndel; uu = nuu;
        B0 = nB0; B1 = nB1; C0 = nC0; C1 = nC1;
    }
}

// ---------------- gate: y *= silu(res) ----------------
__global__ void gate_kernel(float* __restrict__ y, const float* __restrict__ xr) {
    int i = blockIdx.x * blockDim.x + threadIdx.x;
    if (i >= BL * DI) return;
    int r = i / DI, c = i % DI;
    float res = xr[(size_t)r * (2 * DI) + DI + c];
    y[i] *= res / (1.f + expf(-res));
}

// ---------------- host orchestration ----------------
extern "C" void kernel_launch(void* const* d_in, const int* in_sizes, int n_in,
                              void* d_out, int out_size) {
    const int*   ids       = (const int*)  d_in[0];
    const float* emb       = (const float*)d_in[4];
    const float* norm_w    = (const float*)d_in[5];
    const float* in_proj_w = (const float*)d_in[6];
    const float* conv_w    = (const float*)d_in[7];
    const float* conv_b    = (const float*)d_in[8];
    const float* x_proj_w  = (const float*)d_in[9];
    const float* dt_proj_w = (const float*)d_in[10];
    const float* dt_proj_b = (const float*)d_in[11];
    const float* A_log     = (const float*)d_in[12];
    const float* D_param   = (const float*)d_in[13];
    const float* out_proj_w= (const float*)d_in[14];
    const float* norm_f_w  = (const float*)d_in[15];
    float* out = (float*)d_out;

    float *x, *xn, *xr, *xin, *xdbl, *delta, *y;
    cudaGetSymbolAddress((void**)&x,    g_x);
    cudaGetSymbolAddress((void**)&xn,   g_xn);
    cudaGetSymbolAddress((void**)&xr,   g_xr);
    cudaGetSymbolAddress((void**)&xin,  g_xin);
    cudaGetSymbolAddress((void**)&xdbl, g_xdbl);
    cudaGetSymbolAddress((void**)&delta,g_delta);
    cudaGetSymbolAddress((void**)&y,    g_y);

    embed_kernel<<<(BL * DM + 255) / 256, 256>>>(ids, emb, x);

    for (int L = 0; L < NL; ++L) {
        rmsnorm_kernel<<<BL, 256>>>(x, norm_w + (size_t)L * DM, xn);

        // in_proj: (2048x768) @ (3072x768)^T -> (2048x3072)
        gemm_nt<false><<<dim3(2 * DI / 128, BL / 128), 256>>>(
            xn, DM, in_proj_w + (size_t)L * 2 * DI * DM, DM, xr, 2 * DI, BL, 2 * DI, DM);

        conv_silu_kernel<<<(BL * DI + 255) / 256, 256>>>(
            xr, conv_w + (size_t)L * DI * 4, conv_b + (size_t)L * DI, xin);

        // x_proj: (2048x1536) @ (80x1536)^T -> (2048x80)
        gemm_nt<false><<<dim3(1, BL / 128), 256>>>(
            xin, DI, x_proj_w + (size_t)L * XDW * DI, DI, xdbl, XDW, BL, XDW, DI);

        // dt_proj: (2048x48) @ (1536x48)^T -> (2048x1536)
        gemm_nt<false><<<dim3(DI / 128, BL / 128), 256>>>(
            xdbl, XDW, dt_proj_w + (size_t)L * DI * DTR, DTR, delta, DI, BL, DI, DTR);

        dt_act_kernel<<<(BL * DI + 255) / 256, 256>>>(delta, dt_proj_b + (size_t)L * DI);

        scan_kernel<<<(BB * DI * 2) / 128, 128>>>(
            xin, delta, xdbl, A_log + (size_t)L * DI * DS, D_param + (size_t)L * DI, y);

        gate_kernel<<<(BL * DI + 255) / 256, 256>>>(y, xr);

        // out_proj with residual add into x: (2048x1536) @ (768x1536)^T
        gemm_nt<true><<<dim3(DM / 128, BL / 128), 256>>>(
            y, DI, out_proj_w + (size_t)L * DM * DI, DI, x, DM, BL, DM, DI);
    }

    rmsnorm_kernel<<<BL, 256>>>(x, norm_f_w, xn);

    // lm_head: (2048x768) @ (32000x768)^T -> (2048x32000)
    gemm_nt<false><<<dim3(VOC / 128, BL / 128), 256>>>(
        xn, DM, emb, DM, out, VOC, BL, VOC, DM);
}

// round 2
// speedup vs baseline: 1.3831x; 1.3831x over previous
#include <cuda_runtime.h>
#include <cuda_bf16.h>
#include <math.h>
#include <stdint.h>

#define DM   768
#define DI   1536
#define DS   16
#define DTR  48
#define NL   4
#define VOC  32000
#define BB   2
#define LL   1024
#define BL   (BB*LL)      // 2048
#define XDW  (DTR + 2*DS) // 80

// ---------------- scratch (device globals; no allocation allowed) ----------
__device__ float g_x   [BL*DM];
__device__ float g_xn  [BL*DM];
__device__ float g_xr  [BL*2*DI];
__device__ float g_xin [BL*DI];
__device__ float g_xdbl[BL*XDW];
__device__ float g_delta[BL*DI];
__device__ float g_y   [BL*DI];

// ---------------- embedding lookup ----------------
__global__ void embed_kernel(const int* __restrict__ ids,
                             const float* __restrict__ emb,
                             float* __restrict__ x) {
    int i = blockIdx.x * blockDim.x + threadIdx.x;
    if (i >= BL * DM) return;
    int r = i / DM, c = i % DM;
    x[i] = emb[(size_t)ids[r] * DM + c];
}

// ---------------- rmsnorm (one block per row of 768) ----------------
__global__ __launch_bounds__(256) void rmsnorm_kernel(const float* __restrict__ x,
                                                      const float* __restrict__ w,
                                                      float* __restrict__ o) {
    int row = blockIdx.x;
    const float* xrow = x + (size_t)row * DM;
    float s = 0.f;
    for (int c = threadIdx.x; c < DM; c += 256) { float v = xrow[c]; s = fmaf(v, v, s); }
    #pragma unroll
    for (int off = 16; off; off >>= 1) s += __shfl_xor_sync(0xffffffffu, s, off);
    __shared__ float red[8];
    if ((threadIdx.x & 31) == 0) red[threadIdx.x >> 5] = s;
    __syncthreads();
    float tot = red[0] + red[1] + red[2] + red[3] + red[4] + red[5] + red[6] + red[7];
    float sc = rsqrtf(tot * (1.0f / DM) + 1e-5f);
    for (int c = threadIdx.x; c < DM; c += 256)
        o[(size_t)row * DM + c] = xrow[c] * sc * w[c];
}

// ---------------- tensor-core GEMM via mma.sync bf16, 3-pass split ---------
// C(MxN) = A(MxK) * B(NxK)^T, all fp32 in global. A lda, B ldb, C ldc.
// CTA tile 128x128, BK=16. 256 threads = 8 warps, warp tile 64x32.
// fp32 -> (bf16 hi, bf16 lo) split at smem staging; acc = Ah*Bh + Ah*Bl + Al*Bh.
// M must be multiple of 128, K multiple of 16. N guarded.

__device__ __forceinline__ void mma16816(float* c, const uint32_t* a, const uint32_t* b) {
    asm volatile(
        "mma.sync.aligned.m16n8k16.row.col.f32.bf16.bf16.f32 "
        "{%0,%1,%2,%3}, {%4,%5,%6,%7}, {%8,%9}, {%0,%1,%2,%3};"
        : "+f"(c[0]), "+f"(c[1]), "+f"(c[2]), "+f"(c[3])
        : "r"(a[0]), "r"(a[1]), "r"(a[2]), "r"(a[3]), "r"(b[0]), "r"(b[1]));
}

template<bool ADD>
__global__ __launch_bounds__(256) void gemm_tc(const float* __restrict__ A, int lda,
                                               const float* __restrict__ B, int ldb,
                                               float* __restrict__ C, int ldc,
                                               int M, int N, int K) {
    __shared__ __nv_bfloat16 Ah[128][18];
    __shared__ __nv_bfloat16 Al[128][18];
    __shared__ __nv_bfloat16 Bh[128][18];
    __shared__ __nv_bfloat16 Bl[128][18];

    int tid = threadIdx.x;
    int m0 = blockIdx.y * 128;
    int n0 = blockIdx.x * 128;

    // ---- loader mapping: each thread handles one row-half (8 floats) of A and B
    int lrow = tid >> 1;            // 0..127
    int lcol = (tid & 1) * 8;       // 0 or 8

    const float* Aptr = A + (size_t)(m0 + lrow) * lda + lcol;
    bool bvalid = (n0 + lrow) < N;
    const float* Bptr = B + (size_t)(bvalid ? (n0 + lrow) : 0) * ldb + lcol;

    float abuf[8], bbuf[8];
    // prologue: load k-tile 0
    {
        float4 v0 = *(const float4*)(Aptr);
        float4 v1 = *(const float4*)(Aptr + 4);
        abuf[0]=v0.x; abuf[1]=v0.y; abuf[2]=v0.z; abuf[3]=v0.w;
        abuf[4]=v1.x; abuf[5]=v1.y; abuf[6]=v1.z; abuf[7]=v1.w;
        float4 w0 = make_float4(0,0,0,0), w1 = make_float4(0,0,0,0);
        if (bvalid) { w0 = *(const float4*)(Bptr); w1 = *(const float4*)(Bptr + 4); }
        bbuf[0]=w0.x; bbuf[1]=w0.y; bbuf[2]=w0.z; bbuf[3]=w0.w;
        bbuf[4]=w1.x; bbuf[5]=w1.y; bbuf[6]=w1.z; bbuf[7]=w1.w;
    }

    // ---- compute mapping
    int lane = tid & 31;
    int w = tid >> 5;
    int wm = (w & 1) * 64;          // warp row offset in CTA tile
    int wn = (w >> 1) * 32;         // warp col offset
    int g = lane >> 2;              // 0..7
    int tig = lane & 3;             // 0..3

    float acc[4][4][4];
    #pragma unroll
    for (int i = 0; i < 4; i++)
        #pragma unroll
        for (int j = 0; j < 4; j++)
            #pragma unroll
            for (int r = 0; r < 4; r++) acc[i][j][r] = 0.f;

    int KT = K / 16;
    for (int kt = 0; kt < KT; ++kt) {
        // store current buffers (split fp32 -> bf16 hi/lo) into smem
        #pragma unroll
        for (int j = 0; j < 8; j++) {
            float va = abuf[j];
            __nv_bfloat16 h = __float2bfloat16_rn(va);
            Ah[lrow][lcol + j] = h;
            Al[lrow][lcol + j] = __float2bfloat16_rn(va - __bfloat162float(h));
            float vb = bbuf[j];
            __nv_bfloat16 hb = __float2bfloat16_rn(vb);
            Bh[lrow][lcol + j] = hb;
            Bl[lrow][lcol + j] = __float2bfloat16_rn(vb - __bfloat162float(hb));
        }
        __syncthreads();

        // prefetch next k-tile to registers (overlaps with mma below)
        if (kt + 1 < KT) {
            const float* ap = Aptr + (size_t)(kt + 1) * 16;
            float4 v0 = *(const float4*)(ap);
            float4 v1 = *(const float4*)(ap + 4);
            abuf[0]=v0.x; abuf[1]=v0.y; abuf[2]=v0.z; abuf[3]=v0.w;
            abuf[4]=v1.x; abuf[5]=v1.y; abuf[6]=v1.z; abuf[7]=v1.w;
            float4 w0 = make_float4(0,0,0,0), w1 = make_float4(0,0,0,0);
            if (bvalid) {
                const float* bp = Bptr + (size_t)(kt + 1) * 16;
                w0 = *(const float4*)(bp); w1 = *(const float4*)(bp + 4);
            }
            bbuf[0]=w0.x; bbuf[1]=w0.y; bbuf[2]=w0.z; bbuf[3]=w0.w;
            bbuf[4]=w1.x; bbuf[5]=w1.y; bbuf[6]=w1.z; bbuf[7]=w1.w;
        }

        // load fragments
        uint32_t fah[4][4], fal[4][4], fbh[4][2], fbl[4][2];
        #pragma unroll
        for (int mt = 0; mt < 4; mt++) {
            int r = wm + mt * 16 + g;
            fah[mt][0] = *(const uint32_t*)&Ah[r    ][2 * tig];
            fah[mt][1] = *(const uint32_t*)&Ah[r + 8][2 * tig];
            fah[mt][2] = *(const uint32_t*)&Ah[r    ][2 * tig + 8];
            fah[mt][3] = *(const uint32_t*)&Ah[r + 8][2 * tig + 8];
            fal[mt][0] = *(const uint32_t*)&Al[r    ][2 * tig];
            fal[mt][1] = *(const uint32_t*)&Al[r + 8][2 * tig];
            fal[mt][2] = *(const uint32_t*)&Al[r    ][2 * tig + 8];
            fal[mt][3] = *(const uint32_t*)&Al[r + 8][2 * tig + 8];
        }
        #pragma unroll
        for (int nt = 0; nt < 4; nt++) {
            int c = wn + nt * 8 + g;
            fbh[nt][0] = *(const uint32_t*)&Bh[c][2 * tig];
            fbh[nt][1] = *(const uint32_t*)&Bh[c][2 * tig + 8];
            fbl[nt][0] = *(const uint32_t*)&Bl[c][2 * tig];
            fbl[nt][1] = *(const uint32_t*)&Bl[c][2 * tig + 8];
        }

        // 3 compensation passes
        #pragma unroll
        for (int mt = 0; mt < 4; mt++)
            #pragma unroll
            for (int nt = 0; nt < 4; nt++)
                mma16816(acc[mt][nt], fah[mt], fbh[nt]);
        #pragma unroll
        for (int mt = 0; mt < 4; mt++)
            #pragma unroll
            for (int nt = 0; nt < 4; nt++)
                mma16816(acc[mt][nt], fah[mt], fbl[nt]);
        #pragma unroll
        for (int mt = 0; mt < 4; mt++)
            #pragma unroll
            for (int nt = 0; nt < 4; nt++)
                mma16816(acc[mt][nt], fal[mt], fbh[nt]);

        __syncthreads();
    }

    // ---- epilogue
    #pragma unroll
    for (int mt = 0; mt < 4; mt++) {
        #pragma unroll
        for (int nt = 0; nt < 4; nt++) {
            int r = m0 + wm + mt * 16 + g;
            int c = n0 + wn + nt * 8 + 2 * tig;
            float* p0 = C + (size_t)r * ldc + c;
            float* p1 = C + (size_t)(r + 8) * ldc + c;
            if (c < N) {
                if (ADD) { p0[0] += acc[mt][nt][0]; } else { p0[0] = acc[mt][nt][0]; }
                if (ADD) { p1[0] += acc[mt][nt][2]; } else { p1[0] = acc[mt][nt][2]; }
            }
            if (c + 1 < N) {
                if (ADD) { p0[1] += acc[mt][nt][1]; } else { p0[1] = acc[mt][nt][1]; }
                if (ADD) { p1[1] += acc[mt][nt][3]; } else { p1[1] = acc[mt][nt][3]; }
            }
        }
    }
}

// ---------------- causal depthwise conv (D_CONV=4) + SiLU ----------------
__global__ void conv_silu_kernel(const float* __restrict__ xr,
                                 const float* __restrict__ cw,
                                 const float* __restrict__ cb,
                                 float* __restrict__ xin) {
    int i = blockIdx.x * blockDim.x + threadIdx.x;
    if (i >= BL * DI) return;
    int d = i % DI;
    int bl = i / DI;
    int l = bl % LL;
    float w0 = cw[d * 4 + 0], w1 = cw[d * 4 + 1], w2 = cw[d * 4 + 2], w3 = cw[d * 4 + 3];
    const float* base = xr + (size_t)bl * (2 * DI) + d;
    float acc = cb[d];
    if (l >= 3) acc = fmaf(w0, base[-3 * (2 * DI)], acc);
    if (l >= 2) acc = fmaf(w1, base[-2 * (2 * DI)], acc);
    if (l >= 1) acc = fmaf(w2, base[-1 * (2 * DI)], acc);
    acc = fmaf(w3, base[0], acc);
    xin[i] = acc / (1.f + expf(-acc));   // silu
}

// ---------------- dt bias + softplus (in-place on delta) ----------------
__global__ void dt_act_kernel(float* __restrict__ delta, const float* __restrict__ b) {
    int i = blockIdx.x * blockDim.x + threadIdx.x;
    if (i >= BL * DI) return;
    int d = i % DI;
    float v = delta[i] + b[d];
    delta[i] = (v > 0.f) ? v + log1pf(expf(-v)) : log1pf(expf(v));
}

// ---------------- selective scan ----------------
__global__ __launch_bounds__(128) void scan_kernel(const float* __restrict__ u,
                                                   const float* __restrict__ delta,
                                                   const float* __restrict__ xdbl,
                                                   const float* __restrict__ A_log,
                                                   const float* __restrict__ Dp,
                                                   float* __restrict__ y) {
    int tid = blockIdx.x * blockDim.x + threadIdx.x;
    if (tid >= BB * DI * 2) return;
    int half = tid & 1;
    int pair = tid >> 1;
    int d = pair % DI;
    int b = pair / DI;

    float A[8];
    float A0 = -expf(A_log[d * DS]);
    bool structured = true;
    #pragma unroll
    for (int n = 0; n < 8; n++) {
        int ng = half * 8 + n;
        A[n] = -expf(A_log[d * DS + ng]);
        float e = (float)(ng + 1) * A0;
        if (fabsf(A[n] - e) > 1e-3f * fabsf(e)) structured = false;
    }
    float Dd = Dp[d];
    float h[8];
    #pragma unroll
    for (int n = 0; n < 8; n++) h[n] = 0.f;

    const float* up = u + (size_t)b * LL * DI + d;
    const float* dp = delta + (size_t)b * LL * DI + d;
    const float* xp = xdbl + (size_t)b * LL * XDW + DTR + half * 8;
    float* yp = y + (size_t)b * LL * DI + d;

    float del = dp[0], uu = up[0];
    float4 B0 = *(const float4*)(xp);
    float4 B1 = *(const float4*)(xp + 4);
    float4 C0 = *(const float4*)(xp + 16);
    float4 C1 = *(const float4*)(xp + 20);

    for (int l = 0; l < LL; ++l) {
        float ndel = 0.f, nuu = 0.f;
        float4 nB0 = B0, nB1 = B1, nC0 = C0, nC1 = C1;
        if (l + 1 < LL) {
            ndel = dp[(size_t)(l + 1) * DI];
            nuu  = up[(size_t)(l + 1) * DI];
            const float* nx = xp + (size_t)(l + 1) * XDW;
            nB0 = *(const float4*)(nx);
            nB1 = *(const float4*)(nx + 4);
            nC0 = *(const float4*)(nx + 16);
            nC1 = *(const float4*)(nx + 20);
        }
        float Ba[8] = {B0.x, B0.y, B0.z, B0.w, B1.x, B1.y, B1.z, B1.w};
        float Ca[8] = {C0.x, C0.y, C0.z, C0.w, C1.x, C1.y, C1.z, C1.w};
        float dbu = del * uu;
        float ys = 0.f;
        if (structured) {
            float t = __expf(A0 * del);
            float p;
            if (half == 0) p = t;
            else { float t2 = t * t, t4 = t2 * t2, t8 = t4 * t4; p = t8 * t; }
            #pragma unroll
            for (int n = 0; n < 8; n++) {
                h[n] = fmaf(p, h[n], dbu * Ba[n]);
                ys = fmaf(h[n], Ca[n], ys);
                p *= t;
            }
        } else {
            #pragma unroll
            for (int n = 0; n < 8; n++) {
                float dA = __expf(A[n] * del);
                h[n] = fmaf(dA, h[n], dbu * Ba[n]);
                ys = fmaf(h[n], Ca[n], ys);
            }
        }
        ys += __shfl_xor_sync(0xffffffffu, ys, 1);
        if (half == 0) yp[(size_t)l * DI] = fmaf(uu, Dd, ys);
        del = ndel; uu = nuu;
        B0 = nB0; B1 = nB1; C0 = nC0; C1 = nC1;
    }
}

// ---------------- gate: y *= silu(res) ----------------
__global__ void gate_kernel(float* __restrict__ y, const float* __restrict__ xr) {
    int i = blockIdx.x * blockDim.x + threadIdx.x;
    if (i >= BL * DI) return;
    int r = i / DI, c = i % DI;
    float res = xr[(size_t)r * (2 * DI) + DI + c];
    y[i] *= res / (1.f + expf(-res));
}

// ---------------- host orchestration ----------------
extern "C" void kernel_launch(void* const* d_in, const int* in_sizes, int n_in,
                              void* d_out, int out_size) {
    const int*   ids       = (const int*)  d_in[0];
    const float* emb       = (const float*)d_in[4];
    const float* norm_w    = (const float*)d_in[5];
    const float* in_proj_w = (const float*)d_in[6];
    const float* conv_w    = (const float*)d_in[7];
    const float* conv_b    = (const float*)d_in[8];
    const float* x_proj_w  = (const float*)d_in[9];
    const float* dt_proj_w = (const float*)d_in[10];
    const float* dt_proj_b = (const float*)d_in[11];
    const float* A_log     = (const float*)d_in[12];
    const float* D_param   = (const float*)d_in[13];
    const float* out_proj_w= (const float*)d_in[14];
    const float* norm_f_w  = (const float*)d_in[15];
    float* out = (float*)d_out;

    float *x, *xn, *xr, *xin, *xdbl, *delta, *y;
    cudaGetSymbolAddress((void**)&x,    g_x);
    cudaGetSymbolAddress((void**)&xn,   g_xn);
    cudaGetSymbolAddress((void**)&xr,   g_xr);
    cudaGetSymbolAddress((void**)&xin,  g_xin);
    cudaGetSymbolAddress((void**)&xdbl, g_xdbl);
    cudaGetSymbolAddress((void**)&delta,g_delta);
    cudaGetSymbolAddress((void**)&y,    g_y);

    embed_kernel<<<(BL * DM + 255) / 256, 256>>>(ids, emb, x);

    for (int L = 0; L < NL; ++L) {
        rmsnorm_kernel<<<BL, 256>>>(x, norm_w + (size_t)L * DM, xn);

        // in_proj: (2048x768) @ (3072x768)^T -> (2048x3072)
        gemm_tc<false><<<dim3(2 * DI / 128, BL / 128), 256>>>(
            xn, DM, in_proj_w + (size_t)L * 2 * DI * DM, DM, xr, 2 * DI, BL, 2 * DI, DM);

        conv_silu_kernel<<<(BL * DI + 255) / 256, 256>>>(
            xr, conv_w + (size_t)L * DI * 4, conv_b + (size_t)L * DI, xin);

        // x_proj: (2048x1536) @ (80x1536)^T -> (2048x80)
        gemm_tc<false><<<dim3(1, BL / 128), 256>>>(
            xin, DI, x_proj_w + (size_t)L * XDW * DI, DI, xdbl, XDW, BL, XDW, DI);

        // dt_proj: (2048x48) @ (1536x48)^T -> (2048x1536)
        gemm_tc<false><<<dim3(DI / 128, BL / 128), 256>>>(
            xdbl, XDW, dt_proj_w + (size_t)L * DI * DTR, DTR, delta, DI, BL, DI, DTR);

        dt_act_kernel<<<(BL * DI + 255) / 256, 256>>>(delta, dt_proj_b + (size_t)L * DI);

        scan_kernel<<<(BB * DI * 2) / 128, 128>>>(
            xin, delta, xdbl, A_log + (size_t)L * DI * DS, D_param + (size_t)L * DI, y);

        gate_kernel<<<(BL * DI + 255) / 256, 256>>>(y, xr);

        // out_proj with residual add into x: (2048x1536) @ (768x1536)^T
        gemm_tc<true><<<dim3(DM / 128, BL / 128), 256>>>(
            y, DI, out_proj_w + (size_t)L * DM * DI, DI, x, DM, BL, DM, DI);
    }

    rmsnorm_kernel<<<BL, 256>>>(x, norm_f_w, xn);

    // lm_head: (2048x768) @ (32000x768)^T -> (2048x32000)
    gemm_tc<false><<<dim3(VOC / 128, BL / 128), 256>>>(
        xn, DM, emb, DM, out, VOC, BL, VOC, DM);
}

// round 4
// speedup vs baseline: 1.6852x; 1.2184x over previous
#include <cuda_runtime.h>
#include <cuda_bf16.h>
#include <math.h>
#include <stdint.h>

#define DM   768
#define DI   1536
#define DS   16
#define DTR  48
#define NL   4
#define VOC  32000
#define BB   2
#define LL   1024
#define BL   (BB*LL)      // 2048
#define XDW  (DTR + 2*DS) // 80

// ---------------- fp32 scratch ----------------
__device__ float g_x   [BL*DM];
__device__ float g_xn  [BL*DM];
__device__ float g_xr  [BL*2*DI];
__device__ float g_xin [BL*DI];
__device__ float g_xdbl[BL*XDW];
__device__ float g_delta[BL*DI];
__device__ float g_y   [BL*DI];

// ---------------- bf16 hi/lo split scratch (row-major, padded) -------------
__device__ __align__(16) __nv_bfloat16 g_Emb_h [VOC*DM];
__device__ __align__(16) __nv_bfloat16 g_Emb_l [VOC*DM];
__device__ __align__(16) __nv_bfloat16 g_Win_h [NL*2*DI*DM];
__device__ __align__(16) __nv_bfloat16 g_Win_l [NL*2*DI*DM];
__device__ __align__(16) __nv_bfloat16 g_Wout_h[NL*DM*DI];
__device__ __align__(16) __nv_bfloat16 g_Wout_l[NL*DM*DI];
__device__ __align__(16) __nv_bfloat16 g_Wx_h  [NL*128*DI];   // 80 rows padded to 128
__device__ __align__(16) __nv_bfloat16 g_Wx_l  [NL*128*DI];
__device__ __align__(16) __nv_bfloat16 g_Wdt_h [NL*DI*64];    // K=48 padded to 64
__device__ __align__(16) __nv_bfloat16 g_Wdt_l [NL*DI*64];
__device__ __align__(16) __nv_bfloat16 g_Xn_h  [BL*DM];
__device__ __align__(16) __nv_bfloat16 g_Xn_l  [BL*DM];
__device__ __align__(16) __nv_bfloat16 g_Xin_h [BL*DI];
__device__ __align__(16) __nv_bfloat16 g_Xin_l [BL*DI];
__device__ __align__(16) __nv_bfloat16 g_Xd_h  [BL*64];
__device__ __align__(16) __nv_bfloat16 g_Xd_l  [BL*64];
__device__ __align__(16) __nv_bfloat16 g_Y_h   [BL*DI];
__device__ __align__(16) __nv_bfloat16 g_Y_l   [BL*DI];

// ================= split: fp32 -> bf16 hi/lo, padded row-major =============
__global__ void split_kernel(const float* __restrict__ src, int lda, int M, int K,
                             __nv_bfloat16* __restrict__ dhi,
                             __nv_bfloat16* __restrict__ dlo, int Mp, int Kp) {
    int idx = blockIdx.x * blockDim.x + threadIdx.x;
    int nkg = Kp >> 3;
    if (idx >= Mp * nkg) return;
    int r = idx / nkg;
    int k0 = (idx % nkg) << 3;
    __align__(16) __nv_bfloat16 hi[8], lo[8];
    #pragma unroll
    for (int j = 0; j < 8; j++) {
        int k = k0 + j;
        float v = (r < M && k < K) ? src[(size_t)r * lda + k] : 0.f;
        __nv_bfloat16 h = __float2bfloat16_rn(v);
        hi[j] = h;
        lo[j] = __float2bfloat16_rn(v - __bfloat162float(h));
    }
    size_t o = (size_t)r * Kp + k0;
    *(uint4*)(dhi + o) = *(const uint4*)hi;
    *(uint4*)(dlo + o) = *(const uint4*)lo;
}

// ================= mma.sync GEMM with cp.async double buffering =============
// C(M x N) = A(M x K) * B(N x K)^T, 3-pass hi/lo compensation.
// CTA tile 128x128, BK=32, 256 threads (8 warps, warp tile 64x32).
// smem rows stride 40 bf16 (80B): 16B-aligned for cp.async, conflict-free LDS.

__device__ __forceinline__ void mma16816(float* c, const uint32_t* a, const uint32_t* b) {
    asm volatile(
        "mma.sync.aligned.m16n8k16.row.col.f32.bf16.bf16.f32 "
        "{%0,%1,%2,%3}, {%4,%5,%6,%7}, {%8,%9}, {%0,%1,%2,%3};"
        : "+f"(c[0]), "+f"(c[1]), "+f"(c[2]), "+f"(c[3])
        : "r"(a[0]), "r"(a[1]), "r"(a[2]), "r"(a[3]), "r"(b[0]), "r"(b[1]));
}
__device__ __forceinline__ uint32_t smem_u32(const void* p) {
    uint32_t a;
    asm("{ .reg .u64 t; cvta.to.shared.u64 t, %1; cvt.u32.u64 %0, t; }" : "=r"(a) : "l"(p));
    return a;
}
#define CPA16(dst, src) \
    asm volatile("cp.async.cg.shared.global [%0], [%1], 16;" :: "r"(dst), "l"(src) : "memory")
#define CPA_COMMIT() asm volatile("cp.async.commit_group;" ::: "memory")
#define CPA_WAIT(n)  asm volatile("cp.async.wait_group %0;" :: "n"(n) : "memory")

#define SROW 40                    // bf16 per smem row
#define MATS (128*SROW)            // 5120 bf16 per matrix image

template<bool ADD>
__global__ __launch_bounds__(256) void gemm_mma(const __nv_bfloat16* __restrict__ Ah_,
                                                const __nv_bfloat16* __restrict__ Al_,
                                                const __nv_bfloat16* __restrict__ Bh_,
                                                const __nv_bfloat16* __restrict__ Bl_,
                                                float* __restrict__ C, int ldc,
                                                int N, int Kp) {
    extern __shared__ __nv_bfloat16 sm[];
    uint32_t smb = smem_u32(sm);
    int tid = threadIdx.x;
    int m0 = blockIdx.y * 128, n0 = blockIdx.x * 128;

    int lrow = tid >> 2;              // 0..63
    int lkc = (tid & 3) * 8;          // 0,8,16,24

    int lane = tid & 31;
    int w = tid >> 5;
    int wm = (w & 1) * 64;
    int wn = (w >> 1) * 32;
    int g = lane >> 2;
    int tig = lane & 3;

    float acc[4][4][4];
    #pragma unroll
    for (int i = 0; i < 4; i++)
        #pragma unroll
        for (int j = 0; j < 4; j++)
            #pragma unroll
            for (int r = 0; r < 4; r++) acc[i][j][r] = 0.f;

    auto load_stage = [&](int kt, int s) {
        int k0 = kt * 32;
        #pragma unroll
        for (int h = 0; h < 2; h++) {
            int row = lrow + 64 * h;
            size_t aoff = (size_t)(m0 + row) * Kp + k0 + lkc;
            size_t boff = (size_t)(n0 + row) * Kp + k0 + lkc;
            uint32_t sb = smb + (uint32_t)((s * 4 * MATS + row * SROW + lkc) * 2);
            CPA16(sb,                Ah_ + aoff);
            CPA16(sb + MATS * 2,     Al_ + aoff);
            CPA16(sb + 2 * MATS * 2, Bh_ + boff);
            CPA16(sb + 3 * MATS * 2, Bl_ + boff);
        }
        CPA_COMMIT();
    };

    auto compute_stage = [&](int s) {
        const __nv_bfloat16* Ahs = sm + s * 4 * MATS;
        const __nv_bfloat16* Als = Ahs + MATS;
        const __nv_bfloat16* Bhs = Ahs + 2 * MATS;
        const __nv_bfloat16* Bls = Ahs + 3 * MATS;
        #pragma unroll
        for (int ks = 0; ks < 2; ks++) {
            int cb = ks * 16 + 2 * tig;
            uint32_t fah[4][4], fal[4][4], fbh[4][2], fbl[4][2];
            #pragma unroll
            for (int mt = 0; mt < 4; mt++) {
                int r = wm + mt * 16 + g;
                fah[mt][0] = *(const uint32_t*)&Ahs[r * SROW + cb];
                fah[mt][1] = *(const uint32_t*)&Ahs[(r + 8) * SROW + cb];
                fah[mt][2] = *(const uint32_t*)&Ahs[r * SROW + cb + 8];
                fah[mt][3] = *(const uint32_t*)&Ahs[(r + 8) * SROW + cb + 8];
                fal[mt][0] = *(const uint32_t*)&Als[r * SROW + cb];
                fal[mt][1] = *(const uint32_t*)&Als[(r + 8) * SROW + cb];
                fal[mt][2] = *(const uint32_t*)&Als[r * SROW + cb + 8];
                fal[mt][3] = *(const uint32_t*)&Als[(r + 8) * SROW + cb + 8];
            }
            #pragma unroll
            for (int nt = 0; nt < 4; nt++) {
                int c = wn + nt * 8 + g;
                fbh[nt][0] = *(const uint32_t*)&Bhs[c * SROW + cb];
                fbh[nt][1] = *(const uint32_t*)&Bhs[c * SROW + cb + 8];
                fbl[nt][0] = *(const uint32_t*)&Bls[c * SROW + cb];
                fbl[nt][1] = *(const uint32_t*)&Bls[c * SROW + cb + 8];
            }
            #pragma unroll
            for (int mt = 0; mt < 4; mt++)
                #pragma unroll
                for (int nt = 0; nt < 4; nt++)
                    mma16816(acc[mt][nt], fah[mt], fbh[nt]);
            #pragma unroll
            for (int mt = 0; mt < 4; mt++)
                #pragma unroll
                for (int nt = 0; nt < 4; nt++)
                    mma16816(acc[mt][nt], fal[mt], fbh[nt]);
            #pragma unroll
            for (int mt = 0; mt < 4; mt++)
                #pragma unroll
                for (int nt = 0; nt < 4; nt++)
                    mma16816(acc[mt][nt], fah[mt], fbl[nt]);
        }
    };

    int KT = Kp / 32;
    load_stage(0, 0);
    for (int kt = 0; kt < KT; kt++) {
        int s = kt & 1;
        if (kt + 1 < KT) {
            load_stage(kt + 1, s ^ 1);
            CPA_WAIT(1);
        } else {
            CPA_WAIT(0);
        }
        __syncthreads();
        compute_stage(s);
        __syncthreads();
    }

    // epilogue
    #pragma unroll
    for (int mt = 0; mt < 4; mt++) {
        #pragma unroll
        for (int nt = 0; nt < 4; nt++) {
            int r = m0 + wm + mt * 16 + g;
            int c = n0 + wn + nt * 8 + 2 * tig;
            float* p0 = C + (size_t)r * ldc + c;
            float* p1 = C + (size_t)(r + 8) * ldc + c;
            if (c < N) {
                if (ADD) { p0[0] += acc[mt][nt][0]; p1[0] += acc[mt][nt][2]; }
                else     { p0[0]  = acc[mt][nt][0]; p1[0]  = acc[mt][nt][2]; }
            }
            if (c + 1 < N) {
                if (ADD) { p0[1] += acc[mt][nt][1]; p1[1] += acc[mt][nt][3]; }
                else     { p0[1]  = acc[mt][nt][1]; p1[1]  = acc[mt][nt][3]; }
            }
        }
    }
}

// ================= elementwise kernels =================
__global__ void embed_kernel(const int* __restrict__ ids, const float* __restrict__ emb,
                             float* __restrict__ x) {
    int i = blockIdx.x * blockDim.x + threadIdx.x;
    if (i >= BL * DM) return;
    int r = i / DM, c = i % DM;
    x[i] = emb[(size_t)ids[r] * DM + c];
}

__global__ __launch_bounds__(256) void rmsnorm_kernel(const float* __restrict__ x,
                                                      const float* __restrict__ w,
                                                      float* __restrict__ o) {
    int row = blockIdx.x;
    const float* xrow = x + (size_t)row * DM;
    float s = 0.f;
    for (int c = threadIdx.x; c < DM; c += 256) { float v = xrow[c]; s = fmaf(v, v, s); }
    #pragma unroll
    for (int off = 16; off; off >>= 1) s += __shfl_xor_sync(0xffffffffu, s, off);
    __shared__ float red[8];
    if ((threadIdx.x & 31) == 0) red[threadIdx.x >> 5] = s;
    __syncthreads();
    float tot = red[0] + red[1] + red[2] + red[3] + red[4] + red[5] + red[6] + red[7];
    float sc = rsqrtf(tot * (1.0f / DM) + 1e-5f);
    for (int c = threadIdx.x; c < DM; c += 256)
        o[(size_t)row * DM + c] = xrow[c] * sc * w[c];
}

__global__ void conv_silu_kernel(const float* __restrict__ xr, const float* __restrict__ cw,
                                 const float* __restrict__ cb, float* __restrict__ xin) {
    int i = blockIdx.x * blockDim.x + threadIdx.x;
    if (i >= BL * DI) return;
    int d = i % DI;
    int bl = i / DI;
    int l = bl % LL;
    float w0 = cw[d * 4], w1 = cw[d * 4 + 1], w2 = cw[d * 4 + 2], w3 = cw[d * 4 + 3];
    const float* base = xr + (size_t)bl * (2 * DI) + d;
    float acc = cb[d];
    if (l >= 3) acc = fmaf(w0, base[-3 * (2 * DI)], acc);
    if (l >= 2) acc = fmaf(w1, base[-2 * (2 * DI)], acc);
    if (l >= 1) acc = fmaf(w2, base[-1 * (2 * DI)], acc);
    acc = fmaf(w3, base[0], acc);
    xin[i] = acc / (1.f + expf(-acc));
}

__global__ void dt_act_kernel(float* __restrict__ delta, const float* __restrict__ b) {
    int i = blockIdx.x * blockDim.x + threadIdx.x;
    if (i >= BL * DI) return;
    int d = i % DI;
    float v = delta[i] + b[d];
    delta[i] = (v > 0.f) ? v + log1pf(expf(-v)) : log1pf(expf(v));
}

__global__ __launch_bounds__(128) void scan_kernel(const float* __restrict__ u,
                                                   const float* __restrict__ delta,
                                                   const float* __restrict__ xdbl,
                                                   const float* __restrict__ A_log,
                                                   const float* __restrict__ Dp,
                                                   float* __restrict__ y) {
    int tid = blockIdx.x * blockDim.x + threadIdx.x;
    if (tid >= BB * DI * 2) return;
    int half = tid & 1;
    int pair = tid >> 1;
    int d = pair % DI;
    int b = pair / DI;

    float A[8];
    float A0 = -expf(A_log[d * DS]);
    bool structured = true;
    #pragma unroll
    for (int n = 0; n < 8; n++) {
        int ng = half * 8 + n;
        A[n] = -expf(A_log[d * DS + ng]);
        float e = (float)(ng + 1) * A0;
        if (fabsf(A[n] - e) > 1e-3f * fabsf(e)) structured = false;
    }
    float Dd = Dp[d];
    float h[8];
    #pragma unroll
    for (int n = 0; n < 8; n++) h[n] = 0.f;

    const float* up = u + (size_t)b * LL * DI + d;
    const float* dp = delta + (size_t)b * LL * DI + d;
    const float* xp = xdbl + (size_t)b * LL * XDW + DTR + half * 8;
    float* yp = y + (size_t)b * LL * DI + d;

    float del = dp[0], uu = up[0];
    float4 B0 = *(const float4*)(xp);
    float4 B1 = *(const float4*)(xp + 4);
    float4 C0 = *(const float4*)(xp + 16);
    float4 C1 = *(const float4*)(xp + 20);

    for (int l = 0; l < LL; ++l) {
        float ndel = 0.f, nuu = 0.f;
        float4 nB0 = B0, nB1 = B1, nC0 = C0, nC1 = C1;
        if (l + 1 < LL) {
            ndel = dp[(size_t)(l + 1) * DI];
            nuu  = up[(size_t)(l + 1) * DI];
            const float* nx = xp + (size_t)(l + 1) * XDW;
            nB0 = *(const float4*)(nx);
            nB1 = *(const float4*)(nx + 4);
            nC0 = *(const float4*)(nx + 16);
            nC1 = *(const float4*)(nx + 20);
        }
        float Ba[8] = {B0.x, B0.y, B0.z, B0.w, B1.x, B1.y, B1.z, B1.w};
        float Ca[8] = {C0.x, C0.y, C0.z, C0.w, C1.x, C1.y, C1.z, C1.w};
        float dbu = del * uu;
        float ys = 0.f;
        if (structured) {
            float t = __expf(A0 * del);
            float p;
            if (half == 0) p = t;
            else { float t2 = t * t, t4 = t2 * t2, t8 = t4 * t4; p = t8 * t; }
            #pragma unroll
            for (int n = 0; n < 8; n++) {
                h[n] = fmaf(p, h[n], dbu * Ba[n]);
                ys = fmaf(h[n], Ca[n], ys);
                p *= t;
            }
        } else {
            #pragma unroll
            for (int n = 0; n < 8; n++) {
                float dA = __expf(A[n] * del);
                h[n] = fmaf(dA, h[n], dbu * Ba[n]);
                ys = fmaf(h[n], Ca[n], ys);
            }
        }
        ys += __shfl_xor_sync(0xffffffffu, ys, 1);
        if (half == 0) yp[(size_t)l * DI] = fmaf(uu, Dd, ys);
        del = ndel; uu = nuu;
        B0 = nB0; B1 = nB1; C0 = nC0; C1 = nC1;
    }
}

__global__ void gate_kernel(float* __restrict__ y, const float* __restrict__ xr) {
    int i = blockIdx.x * blockDim.x + threadIdx.x;
    if (i >= BL * DI) return;
    int r = i / DI, c = i % DI;
    float res = xr[(size_t)r * (2 * DI) + DI + c];
    y[i] *= res / (1.f + expf(-res));
}

// ================= host =================
static inline void launch_split(const float* src, int lda, int M, int K,
                                __nv_bfloat16* dhi, __nv_bfloat16* dlo, int Mp, int Kp) {
    int tot = Mp * (Kp / 8);
    split_kernel<<<(tot + 255) / 256, 256>>>(src, lda, M, K, dhi, dlo, Mp, Kp);
}

extern "C" void kernel_launch(void* const* d_in, const int* in_sizes, int n_in,
                              void* d_out, int out_size) {
    const int*   ids       = (const int*)  d_in[0];
    const float* emb       = (const float*)d_in[4];
    const float* norm_w    = (const float*)d_in[5];
    const float* in_proj_w = (const float*)d_in[6];
    const float* conv_w    = (const float*)d_in[7];
    const float* conv_b    = (const float*)d_in[8];
    const float* x_proj_w  = (const float*)d_in[9];
    const float* dt_proj_w = (const float*)d_in[10];
    const float* dt_proj_b = (const float*)d_in[11];
    const float* A_log     = (const float*)d_in[12];
    const float* D_param   = (const float*)d_in[13];
    const float* out_proj_w= (const float*)d_in[14];
    const float* norm_f_w  = (const float*)d_in[15];
    float* out = (float*)d_out;

    float *x, *xn, *xr, *xin, *xdbl, *delta, *y;
    cudaGetSymbolAddress((void**)&x,     g_x);
    cudaGetSymbolAddress((void**)&xn,    g_xn);
    cudaGetSymbolAddress((void**)&xr,    g_xr);
    cudaGetSymbolAddress((void**)&xin,   g_xin);
    cudaGetSymbolAddress((void**)&xdbl,  g_xdbl);
    cudaGetSymbolAddress((void**)&delta, g_delta);
    cudaGetSymbolAddress((void**)&y,     g_y);

    __nv_bfloat16 *Emb_h, *Emb_l, *Win_h, *Win_l, *Wout_h, *Wout_l;
    __nv_bfloat16 *Wx_h, *Wx_l, *Wdt_h, *Wdt_l;
    __nv_bfloat16 *Xn_h, *Xn_l, *Xin_h, *Xin_l, *Xd_h, *Xd_l, *Y_h, *Y_l;
    cudaGetSymbolAddress((void**)&Emb_h,  g_Emb_h);  cudaGetSymbolAddress((void**)&Emb_l,  g_Emb_l);
    cudaGetSymbolAddress((void**)&Win_h,  g_Win_h);  cudaGetSymbolAddress((void**)&Win_l,  g_Win_l);
    cudaGetSymbolAddress((void**)&Wout_h, g_Wout_h); cudaGetSymbolAddress((void**)&Wout_l, g_Wout_l);
    cudaGetSymbolAddress((void**)&Wx_h,   g_Wx_h);   cudaGetSymbolAddress((void**)&Wx_l,   g_Wx_l);
    cudaGetSymbolAddress((void**)&Wdt_h,  g_Wdt_h);  cudaGetSymbolAddress((void**)&Wdt_l,  g_Wdt_l);
    cudaGetSymbolAddress((void**)&Xn_h,   g_Xn_h);   cudaGetSymbolAddress((void**)&Xn_l,   g_Xn_l);
    cudaGetSymbolAddress((void**)&Xin_h,  g_Xin_h);  cudaGetSymbolAddress((void**)&Xin_l,  g_Xin_l);
    cudaGetSymbolAddress((void**)&Xd_h,   g_Xd_h);   cudaGetSymbolAddress((void**)&Xd_l,   g_Xd_l);
    cudaGetSymbolAddress((void**)&Y_h,    g_Y_h);    cudaGetSymbolAddress((void**)&Y_l,    g_Y_l);

    const int SMEM = 2 * 4 * MATS * 2;  // 81920 bytes
    cudaFuncSetAttribute(gemm_mma<false>, cudaFuncAttributeMaxDynamicSharedMemorySize, SMEM);
    cudaFuncSetAttribute(gemm_mma<true>,  cudaFuncAttributeMaxDynamicSharedMemorySize, SMEM);

    // one-time splits: weights + embedding
    for (int L = 0; L < NL; ++L) {
        launch_split(in_proj_w + (size_t)L * 2 * DI * DM, DM, 2 * DI, DM,
                     Win_h + (size_t)L * 2 * DI * DM, Win_l + (size_t)L * 2 * DI * DM, 2 * DI, DM);
        launch_split(out_proj_w + (size_t)L * DM * DI, DI, DM, DI,
                     Wout_h + (size_t)L * DM * DI, Wout_l + (size_t)L * DM * DI, DM, DI);
        launch_split(x_proj_w + (size_t)L * XDW * DI, DI, XDW, DI,
                     Wx_h + (size_t)L * 128 * DI, Wx_l + (size_t)L * 128 * DI, 128, DI);
        launch_split(dt_proj_w + (size_t)L * DI * DTR, DTR, DI, DTR,
                     Wdt_h + (size_t)L * DI * 64, Wdt_l + (size_t)L * DI * 64, DI, 64);
    }
    launch_split(emb, DM, VOC, DM, Emb_h, Emb_l, VOC, DM);

    embed_kernel<<<(BL * DM + 255) / 256, 256>>>(ids, emb, x);

    for (int L = 0; L < NL; ++L) {
        rmsnorm_kernel<<<BL, 256>>>(x, norm_w + (size_t)L * DM, xn);
        launch_split(xn, DM, BL, DM, Xn_h, Xn_l, BL, DM);

        // in_proj: (2048x768) @ (3072x768)^T
        gemm_mma<false><<<dim3(2 * DI / 128, BL / 128), 256, SMEM>>>(
            Xn_h, Xn_l, Win_h + (size_t)L * 2 * DI * DM, Win_l + (size_t)L * 2 * DI * DM,
            xr, 2 * DI, 2 * DI, DM);

        conv_silu_kernel<<<(BL * DI + 255) / 256, 256>>>(
            xr, conv_w + (size_t)L * DI * 4, conv_b + (size_t)L * DI, xin);
        launch_split(xin, DI, BL, DI, Xin_h, Xin_l, BL, DI);

        // x_proj: (2048x1536) @ (80x1536)^T
        gemm_mma<false><<<dim3(1, BL / 128), 256, SMEM>>>(
            Xin_h, Xin_l, Wx_h + (size_t)L * 128 * DI, Wx_l + (size_t)L * 128 * DI,
            xdbl, XDW, XDW, DI);

        launch_split(xdbl, XDW, BL, DTR, Xd_h, Xd_l, BL, 64);

        // dt_proj: (2048x48pad64) @ (1536x48pad64)^T
        gemm_mma<false><<<dim3(DI / 128, BL / 128), 256, SMEM>>>(
            Xd_h, Xd_l, Wdt_h + (size_t)L * DI * 64, Wdt_l + (size_t)L * DI * 64,
            delta, DI, DI, 64);

        dt_act_kernel<<<(BL * DI + 255) / 256, 256>>>(delta, dt_proj_b + (size_t)L * DI);

        scan_kernel<<<(BB * DI * 2) / 128, 128>>>(
            xin, delta, xdbl, A_log + (size_t)L * DI * DS, D_param + (size_t)L * DI, y);

        gate_kernel<<<(BL * DI + 255) / 256, 256>>>(y, xr);
        launch_split(y, DI, BL, DI, Y_h, Y_l, BL, DI);

        // out_proj + residual: (2048x1536) @ (768x1536)^T, ADD into x
        gemm_mma<true><<<dim3(DM / 128, BL / 128), 256, SMEM>>>(
            Y_h, Y_l, Wout_h + (size_t)L * DM * DI, Wout_l + (size_t)L * DM * DI,
            x, DM, DM, DI);
    }

    rmsnorm_kernel<<<BL, 256>>>(x, norm_f_w, xn);
    launch_split(xn, DM, BL, DM, Xn_h, Xn_l, BL, DM);

    // lm_head: (2048x768) @ (32000x768)^T
    gemm_mma<false><<<dim3(VOC / 128, BL / 128), 256, SMEM>>>(
        Xn_h, Xn_l, Emb_h, Emb_l, out, VOC, VOC, DM);
}

// round 5
// speedup vs baseline: 1.6887x; 1.0021x over previous
#include <cuda_runtime.h>
#include <cuda_bf16.h>
#include <math.h>
#include <stdint.h>

#define DM   768
#define DI   1536
#define DS   16
#define DTR  48
#define NL   4
#define VOC  32000
#define BB   2
#define LL   1024
#define BL   (BB*LL)      // 2048
#define XDW  (DTR + 2*DS) // 80

// ---------------- fp32 scratch ----------------
__device__ float g_x   [BL*DM];
__device__ float g_xn  [BL*DM];
__device__ float g_xr  [BL*2*DI];
__device__ float g_xin [BL*DI];
__device__ float g_xdbl[BL*XDW];
__device__ float g_delta[BL*DI];
__device__ float g_y   [BL*DI];

// ---------------- bf16 hi/lo split scratch (row-major, padded) -------------
__device__ __align__(16) __nv_bfloat16 g_Emb_h [VOC*DM];
__device__ __align__(16) __nv_bfloat16 g_Emb_l [VOC*DM];
__device__ __align__(16) __nv_bfloat16 g_Win_h [NL*2*DI*DM];
__device__ __align__(16) __nv_bfloat16 g_Win_l [NL*2*DI*DM];
__device__ __align__(16) __nv_bfloat16 g_Wout_h[NL*DM*DI];
__device__ __align__(16) __nv_bfloat16 g_Wout_l[NL*DM*DI];
__device__ __align__(16) __nv_bfloat16 g_Wx_h  [NL*128*DI];   // 80 rows padded to 128
__device__ __align__(16) __nv_bfloat16 g_Wx_l  [NL*128*DI];
__device__ __align__(16) __nv_bfloat16 g_Wdt_h [NL*DI*64];    // K=48 padded to 64
__device__ __align__(16) __nv_bfloat16 g_Wdt_l [NL*DI*64];
__device__ __align__(16) __nv_bfloat16 g_Xn_h  [BL*DM];
__device__ __align__(16) __nv_bfloat16 g_Xn_l  [BL*DM];
__device__ __align__(16) __nv_bfloat16 g_Xin_h [BL*DI];
__device__ __align__(16) __nv_bfloat16 g_Xin_l [BL*DI];
__device__ __align__(16) __nv_bfloat16 g_Xd_h  [BL*64];
__device__ __align__(16) __nv_bfloat16 g_Xd_l  [BL*64];
__device__ __align__(16) __nv_bfloat16 g_Y_h   [BL*DI];
__device__ __align__(16) __nv_bfloat16 g_Y_l   [BL*DI];

// ================= split: fp32 -> bf16 hi/lo, padded row-major =============
__global__ void split_kernel(const float* __restrict__ src, int lda, int M, int K,
                             __nv_bfloat16* __restrict__ dhi,
                             __nv_bfloat16* __restrict__ dlo, int Mp, int Kp) {
    int idx = blockIdx.x * blockDim.x + threadIdx.x;
    int nkg = Kp >> 3;
    if (idx >= Mp * nkg) return;
    int r = idx / nkg;
    int k0 = (idx % nkg) << 3;
    __align__(16) __nv_bfloat16 hi[8], lo[8];
    #pragma unroll
    for (int j = 0; j < 8; j++) {
        int k = k0 + j;
        float v = (r < M && k < K) ? src[(size_t)r * lda + k] : 0.f;
        __nv_bfloat16 h = __float2bfloat16_rn(v);
        hi[j] = h;
        lo[j] = __float2bfloat16_rn(v - __bfloat162float(h));
    }
    size_t o = (size_t)r * Kp + k0;
    *(uint4*)(dhi + o) = *(const uint4*)hi;
    *(uint4*)(dlo + o) = *(const uint4*)lo;
}

// ================= mma.sync GEMM with cp.async double buffering =============
// C(M x N) = A(M x K) * B(N x K)^T, 3-pass hi/lo compensation.
// CTA tile 128x128, BK=32, 256 threads (8 warps, warp tile 64x32).
// smem rows stride 40 bf16 (80B): 16B-aligned for cp.async, conflict-free LDS.

__device__ __forceinline__ void mma16816(float* c, const uint32_t* a, const uint32_t* b) {
    asm volatile(
        "mma.sync.aligned.m16n8k16.row.col.f32.bf16.bf16.f32 "
        "{%0,%1,%2,%3}, {%4,%5,%6,%7}, {%8,%9}, {%0,%1,%2,%3};"
        : "+f"(c[0]), "+f"(c[1]), "+f"(c[2]), "+f"(c[3])
        : "r"(a[0]), "r"(a[1]), "r"(a[2]), "r"(a[3]), "r"(b[0]), "r"(b[1]));
}
__device__ __forceinline__ uint32_t smem_u32(const void* p) {
    uint32_t a;
    asm("{ .reg .u64 t; cvta.to.shared.u64 t, %1; cvt.u32.u64 %0, t; }" : "=r"(a) : "l"(p));
    return a;
}
#define CPA16(dst, src) \
    asm volatile("cp.async.cg.shared.global [%0], [%1], 16;" :: "r"(dst), "l"(src) : "memory")
#define CPA_COMMIT() asm volatile("cp.async.commit_group;" ::: "memory")
#define CPA_WAIT(n)  asm volatile("cp.async.wait_group %0;" :: "n"(n) : "memory")

#define SROW 40                    // bf16 per smem row
#define MATS (128*SROW)            // 5120 bf16 per matrix image

template<bool ADD>
__global__ __launch_bounds__(256) void gemm_mma(const __nv_bfloat16* __restrict__ Ah_,
                                                const __nv_bfloat16* __restrict__ Al_,
                                                const __nv_bfloat16* __restrict__ Bh_,
                                                const __nv_bfloat16* __restrict__ Bl_,
                                                float* __restrict__ C, int ldc,
                                                int N, int Kp) {
    extern __shared__ __nv_bfloat16 sm[];
    uint32_t smb = smem_u32(sm);
    int tid = threadIdx.x;
    int m0 = blockIdx.y * 128, n0 = blockIdx.x * 128;

    int lrow = tid >> 2;              // 0..63
    int lkc = (tid & 3) * 8;          // 0,8,16,24

    int lane = tid & 31;
    int w = tid >> 5;
    int wm = (w & 1) * 64;
    int wn = (w >> 1) * 32;
    int g = lane >> 2;
    int tig = lane & 3;

    float acc[4][4][4];
    #pragma unroll
    for (int i = 0; i < 4; i++)
        #pragma unroll
        for (int j = 0; j < 4; j++)
            #pragma unroll
            for (int r = 0; r < 4; r++) acc[i][j][r] = 0.f;

    auto load_stage = [&](int kt, int s) {
        int k0 = kt * 32;
        #pragma unroll
        for (int h = 0; h < 2; h++) {
            int row = lrow + 64 * h;
            size_t aoff = (size_t)(m0 + row) * Kp + k0 + lkc;
            size_t boff = (size_t)(n0 + row) * Kp + k0 + lkc;
            uint32_t sb = smb + (uint32_t)((s * 4 * MATS + row * SROW + lkc) * 2);
            CPA16(sb,                Ah_ + aoff);
            CPA16(sb + MATS * 2,     Al_ + aoff);
            CPA16(sb + 2 * MATS * 2, Bh_ + boff);
            CPA16(sb + 3 * MATS * 2, Bl_ + boff);
        }
        CPA_COMMIT();
    };

    auto compute_stage = [&](int s) {
        const __nv_bfloat16* Ahs = sm + s * 4 * MATS;
        const __nv_bfloat16* Als = Ahs + MATS;
        const __nv_bfloat16* Bhs = Ahs + 2 * MATS;
        const __nv_bfloat16* Bls = Ahs + 3 * MATS;
        #pragma unroll
        for (int ks = 0; ks < 2; ks++) {
            int cb = ks * 16 + 2 * tig;
            uint32_t fah[4][4], fal[4][4], fbh[4][2], fbl[4][2];
            #pragma unroll
            for (int mt = 0; mt < 4; mt++) {
                int r = wm + mt * 16 + g;
                fah[mt][0] = *(const uint32_t*)&Ahs[r * SROW + cb];
                fah[mt][1] = *(const uint32_t*)&Ahs[(r + 8) * SROW + cb];
                fah[mt][2] = *(const uint32_t*)&Ahs[r * SROW + cb + 8];
                fah[mt][3] = *(const uint32_t*)&Ahs[(r + 8) * SROW + cb + 8];
                fal[mt][0] = *(const uint32_t*)&Als[r * SROW + cb];
                fal[mt][1] = *(const uint32_t*)&Als[(r + 8) * SROW + cb];
                fal[mt][2] = *(const uint32_t*)&Als[r * SROW + cb + 8];
                fal[mt][3] = *(const uint32_t*)&Als[(r + 8) * SROW + cb + 8];
            }
            #pragma unroll
            for (int nt = 0; nt < 4; nt++) {
                int c = wn + nt * 8 + g;
                fbh[nt][0] = *(const uint32_t*)&Bhs[c * SROW + cb];
                fbh[nt][1] = *(const uint32_t*)&Bhs[c * SROW + cb + 8];
                fbl[nt][0] = *(const uint32_t*)&Bls[c * SROW + cb];
                fbl[nt][1] = *(const uint32_t*)&Bls[c * SROW + cb + 8];
            }
            #pragma unroll
            for (int mt = 0; mt < 4; mt++)
                #pragma unroll
                for (int nt = 0; nt < 4; nt++)
                    mma16816(acc[mt][nt], fah[mt], fbh[nt]);
            #pragma unroll
            for (int mt = 0; mt < 4; mt++)
                #pragma unroll
                for (int nt = 0; nt < 4; nt++)
                    mma16816(acc[mt][nt], fal[mt], fbh[nt]);
            #pragma unroll
            for (int mt = 0; mt < 4; mt++)
                #pragma unroll
                for (int nt = 0; nt < 4; nt++)
                    mma16816(acc[mt][nt], fah[mt], fbl[nt]);
        }
    };

    int KT = Kp / 32;
    load_stage(0, 0);
    for (int kt = 0; kt < KT; kt++) {
        int s = kt & 1;
        if (kt + 1 < KT) {
            load_stage(kt + 1, s ^ 1);
            CPA_WAIT(1);
        } else {
            CPA_WAIT(0);
        }
        __syncthreads();
        compute_stage(s);
        __syncthreads();
    }

    // epilogue
    #pragma unroll
    for (int mt = 0; mt < 4; mt++) {
        #pragma unroll
        for (int nt = 0; nt < 4; nt++) {
            int r = m0 + wm + mt * 16 + g;
            int c = n0 + wn + nt * 8 + 2 * tig;
            float* p0 = C + (size_t)r * ldc + c;
            float* p1 = C + (size_t)(r + 8) * ldc + c;
            if (c < N) {
                if (ADD) { p0[0] += acc[mt][nt][0]; p1[0] += acc[mt][nt][2]; }
                else     { p0[0]  = acc[mt][nt][0]; p1[0]  = acc[mt][nt][2]; }
            }
            if (c + 1 < N) {
                if (ADD) { p0[1] += acc[mt][nt][1]; p1[1] += acc[mt][nt][3]; }
                else     { p0[1]  = acc[mt][nt][1]; p1[1]  = acc[mt][nt][3]; }
            }
        }
    }
}

// ================= elementwise kernels =================
__global__ void embed_kernel(const int* __restrict__ ids, const float* __restrict__ emb,
                             float* __restrict__ x) {
    int i = blockIdx.x * blockDim.x + threadIdx.x;
    if (i >= BL * DM) return;
    int r = i / DM, c = i % DM;
    x[i] = emb[(size_t)ids[r] * DM + c];
}

__global__ __launch_bounds__(256) void rmsnorm_kernel(const float* __restrict__ x,
                                                      const float* __restrict__ w,
                                                      float* __restrict__ o) {
    int row = blockIdx.x;
    const float* xrow = x + (size_t)row * DM;
    float s = 0.f;
    for (int c = threadIdx.x; c < DM; c += 256) { float v = xrow[c]; s = fmaf(v, v, s); }
    #pragma unroll
    for (int off = 16; off; off >>= 1) s += __shfl_xor_sync(0xffffffffu, s, off);
    __shared__ float red[8];
    if ((threadIdx.x & 31) == 0) red[threadIdx.x >> 5] = s;
    __syncthreads();
    float tot = red[0] + red[1] + red[2] + red[3] + red[4] + red[5] + red[6] + red[7];
    float sc = rsqrtf(tot * (1.0f / DM) + 1e-5f);
    for (int c = threadIdx.x; c < DM; c += 256)
        o[(size_t)row * DM + c] = xrow[c] * sc * w[c];
}

__global__ void conv_silu_kernel(const float* __restrict__ xr, const float* __restrict__ cw,
                                 const float* __restrict__ cb, float* __restrict__ xin) {
    int i = blockIdx.x * blockDim.x + threadIdx.x;
    if (i >= BL * DI) return;
    int d = i % DI;
    int bl = i / DI;
    int l = bl % LL;
    float w0 = cw[d * 4], w1 = cw[d * 4 + 1], w2 = cw[d * 4 + 2], w3 = cw[d * 4 + 3];
    const float* base = xr + (size_t)bl * (2 * DI) + d;
    float acc = cb[d];
    if (l >= 3) acc = fmaf(w0, base[-3 * (2 * DI)], acc);
    if (l >= 2) acc = fmaf(w1, base[-2 * (2 * DI)], acc);
    if (l >= 1) acc = fmaf(w2, base[-1 * (2 * DI)], acc);
    acc = fmaf(w3, base[0], acc);
    xin[i] = acc / (1.f + expf(-acc));
}

__global__ void dt_act_kernel(float* __restrict__ delta, const float* __restrict__ b) {
    int i = blockIdx.x * blockDim.x + threadIdx.x;
    if (i >= BL * DI) return;
    int d = i % DI;
    float v = delta[i] + b[d];
    delta[i] = (v > 0.f) ? v + log1pf(expf(-v)) : log1pf(expf(v));
}

__global__ __launch_bounds__(128) void scan_kernel(const float* __restrict__ u,
                                                   const float* __restrict__ delta,
                                                   const float* __restrict__ xdbl,
                                                   const float* __restrict__ A_log,
                                                   const float* __restrict__ Dp,
                                                   float* __restrict__ y) {
    int tid = blockIdx.x * blockDim.x + threadIdx.x;
    if (tid >= BB * DI * 2) return;
    int half = tid & 1;
    int pair = tid >> 1;
    int d = pair % DI;
    int b = pair / DI;

    float A[8];
    float A0 = -expf(A_log[d * DS]);
    bool structured = true;
    #pragma unroll
    for (int n = 0; n < 8; n++) {
        int ng = half * 8 + n;
        A[n] = -expf(A_log[d * DS + ng]);
        float e = (float)(ng + 1) * A0;
        if (fabsf(A[n] - e) > 1e-3f * fabsf(e)) structured = false;
    }
    float Dd = Dp[d];
    float h[8];
    #pragma unroll
    for (int n = 0; n < 8; n++) h[n] = 0.f;

    const float* up = u + (size_t)b * LL * DI + d;
    const float* dp = delta + (size_t)b * LL * DI + d;
    const float* xp = xdbl + (size_t)b * LL * XDW + DTR + half * 8;
    float* yp = y + (size_t)b * LL * DI + d;

    float del = dp[0], uu = up[0];
    float4 B0 = *(const float4*)(xp);
    float4 B1 = *(const float4*)(xp + 4);
    float4 C0 = *(const float4*)(xp + 16);
    float4 C1 = *(const float4*)(xp + 20);

    for (int l = 0; l < LL; ++l) {
        float ndel = 0.f, nuu = 0.f;
        float4 nB0 = B0, nB1 = B1, nC0 = C0, nC1 = C1;
        if (l + 1 < LL) {
            ndel = dp[(size_t)(l + 1) * DI];
            nuu  = up[(size_t)(l + 1) * DI];
            const float* nx = xp + (size_t)(l + 1) * XDW;
            nB0 = *(const float4*)(nx);
            nB1 = *(const float4*)(nx + 4);
            nC0 = *(const float4*)(nx + 16);
            nC1 = *(const float4*)(nx + 20);
        }
        float Ba[8] = {B0.x, B0.y, B0.z, B0.w, B1.x, B1.y, B1.z, B1.w};
        float Ca[8] = {C0.x, C0.y, C0.z, C0.w, C1.x, C1.y, C1.z, C1.w};
        float dbu = del * uu;
        float ys = 0.f;
        if (structured) {
            float t = __expf(A0 * del);
            float p;
            if (half == 0) p = t;
            else { float t2 = t * t, t4 = t2 * t2, t8 = t4 * t4; p = t8 * t; }
            #pragma unroll
            for (int n = 0; n < 8; n++) {
                h[n] = fmaf(p, h[n], dbu * Ba[n]);
                ys = fmaf(h[n], Ca[n], ys);
                p *= t;
            }
        } else {
            #pragma unroll
            for (int n = 0; n < 8; n++) {
                float dA = __expf(A[n] * del);
                h[n] = fmaf(dA, h[n], dbu * Ba[n]);
                ys = fmaf(h[n], Ca[n], ys);
            }
        }
        ys += __shfl_xor_sync(0xffffffffu, ys, 1);
        if (half == 0) yp[(size_t)l * DI] = fmaf(uu, Dd, ys);
        del = ndel; uu = nuu;
        B0 = nB0; B1 = nB1; C0 = nC0; C1 = nC1;
    }
}

__global__ void gate_kernel(float* __restrict__ y, const float* __restrict__ xr) {
    int i = blockIdx.x * blockDim.x + threadIdx.x;
    if (i >= BL * DI) return;
    int r = i / DI, c = i % DI;
    float res = xr[(size_t)r * (2 * DI) + DI + c];
    y[i] *= res / (1.f + expf(-res));
}

// ================= host =================
static inline void launch_split(const float* src, int lda, int M, int K,
                                __nv_bfloat16* dhi, __nv_bfloat16* dlo, int Mp, int Kp) {
    int tot = Mp * (Kp / 8);
    split_kernel<<<(tot + 255) / 256, 256>>>(src, lda, M, K, dhi, dlo, Mp, Kp);
}

extern "C" void kernel_launch(void* const* d_in, const int* in_sizes, int n_in,
                              void* d_out, int out_size) {
    const int*   ids       = (const int*)  d_in[0];
    const float* emb       = (const float*)d_in[4];
    const float* norm_w    = (const float*)d_in[5];
    const float* in_proj_w = (const float*)d_in[6];
    const float* conv_w    = (const float*)d_in[7];
    const float* conv_b    = (const float*)d_in[8];
    const float* x_proj_w  = (const float*)d_in[9];
    const float* dt_proj_w = (const float*)d_in[10];
    const float* dt_proj_b = (const float*)d_in[11];
    const float* A_log     = (const float*)d_in[12];
    const float* D_param   = (const float*)d_in[13];
    const float* out_proj_w= (const float*)d_in[14];
    const float* norm_f_w  = (const float*)d_in[15];
    float* out = (float*)d_out;

    float *x, *xn, *xr, *xin, *xdbl, *delta, *y;
    cudaGetSymbolAddress((void**)&x,     g_x);
    cudaGetSymbolAddress((void**)&xn,    g_xn);
    cudaGetSymbolAddress((void**)&xr,    g_xr);
    cudaGetSymbolAddress((void**)&xin,   g_xin);
    cudaGetSymbolAddress((void**)&xdbl,  g_xdbl);
    cudaGetSymbolAddress((void**)&delta, g_delta);
    cudaGetSymbolAddress((void**)&y,     g_y);

    __nv_bfloat16 *Emb_h, *Emb_l, *Win_h, *Win_l, *Wout_h, *Wout_l;
    __nv_bfloat16 *Wx_h, *Wx_l, *Wdt_h, *Wdt_l;
    __nv_bfloat16 *Xn_h, *Xn_l, *Xin_h, *Xin_l, *Xd_h, *Xd_l, *Y_h, *Y_l;
    cudaGetSymbolAddress((void**)&Emb_h,  g_Emb_h);  cudaGetSymbolAddress((void**)&Emb_l,  g_Emb_l);
    cudaGetSymbolAddress((void**)&Win_h,  g_Win_h);  cudaGetSymbolAddress((void**)&Win_l,  g_Win_l);
    cudaGetSymbolAddress((void**)&Wout_h, g_Wout_h); cudaGetSymbolAddress((void**)&Wout_l, g_Wout_l);
    cudaGetSymbolAddress((void**)&Wx_h,   g_Wx_h);   cudaGetSymbolAddress((void**)&Wx_l,   g_Wx_l);
    cudaGetSymbolAddress((void**)&Wdt_h,  g_Wdt_h);  cudaGetSymbolAddress((void**)&Wdt_l,  g_Wdt_l);
    cudaGetSymbolAddress((void**)&Xn_h,   g_Xn_h);   cudaGetSymbolAddress((void**)&Xn_l,   g_Xn_l);
    cudaGetSymbolAddress((void**)&Xin_h,  g_Xin_h);  cudaGetSymbolAddress((void**)&Xin_l,  g_Xin_l);
    cudaGetSymbolAddress((void**)&Xd_h,   g_Xd_h);   cudaGetSymbolAddress((void**)&Xd_l,   g_Xd_l);
    cudaGetSymbolAddress((void**)&Y_h,    g_Y_h);    cudaGetSymbolAddress((void**)&Y_l,    g_Y_l);

    const int SMEM = 2 * 4 * MATS * 2;  // 81920 bytes
    cudaFuncSetAttribute(gemm_mma<false>, cudaFuncAttributeMaxDynamicSharedMemorySize, SMEM);
    cudaFuncSetAttribute(gemm_mma<true>,  cudaFuncAttributeMaxDynamicSharedMemorySize, SMEM);

    // one-time splits: weights + embedding
    for (int L = 0; L < NL; ++L) {
        launch_split(in_proj_w + (size_t)L * 2 * DI * DM, DM, 2 * DI, DM,
                     Win_h + (size_t)L * 2 * DI * DM, Win_l + (size_t)L * 2 * DI * DM, 2 * DI, DM);
        launch_split(out_proj_w + (size_t)L * DM * DI, DI, DM, DI,
                     Wout_h + (size_t)L * DM * DI, Wout_l + (size_t)L * DM * DI, DM, DI);
        launch_split(x_proj_w + (size_t)L * XDW * DI, DI, XDW, DI,
                     Wx_h + (size_t)L * 128 * DI, Wx_l + (size_t)L * 128 * DI, 128, DI);
        launch_split(dt_proj_w + (size_t)L * DI * DTR, DTR, DI, DTR,
                     Wdt_h + (size_t)L * DI * 64, Wdt_l + (size_t)L * DI * 64, DI, 64);
    }
    launch_split(emb, DM, VOC, DM, Emb_h, Emb_l, VOC, DM);

    embed_kernel<<<(BL * DM + 255) / 256, 256>>>(ids, emb, x);

    for (int L = 0; L < NL; ++L) {
        rmsnorm_kernel<<<BL, 256>>>(x, norm_w + (size_t)L * DM, xn);
        launch_split(xn, DM, BL, DM, Xn_h, Xn_l, BL, DM);

        // in_proj: (2048x768) @ (3072x768)^T
        gemm_mma<false><<<dim3(2 * DI / 128, BL / 128), 256, SMEM>>>(
            Xn_h, Xn_l, Win_h + (size_t)L * 2 * DI * DM, Win_l + (size_t)L * 2 * DI * DM,
            xr, 2 * DI, 2 * DI, DM);

        conv_silu_kernel<<<(BL * DI + 255) / 256, 256>>>(
            xr, conv_w + (size_t)L * DI * 4, conv_b + (size_t)L * DI, xin);
        launch_split(xin, DI, BL, DI, Xin_h, Xin_l, BL, DI);

        // x_proj: (2048x1536) @ (80x1536)^T
        gemm_mma<false><<<dim3(1, BL / 128), 256, SMEM>>>(
            Xin_h, Xin_l, Wx_h + (size_t)L * 128 * DI, Wx_l + (size_t)L * 128 * DI,
            xdbl, XDW, XDW, DI);

        launch_split(xdbl, XDW, BL, DTR, Xd_h, Xd_l, BL, 64);

        // dt_proj: (2048x48pad64) @ (1536x48pad64)^T
        gemm_mma<false><<<dim3(DI / 128, BL / 128), 256, SMEM>>>(
            Xd_h, Xd_l, Wdt_h + (size_t)L * DI * 64, Wdt_l + (size_t)L * DI * 64,
            delta, DI, DI, 64);

        dt_act_kernel<<<(BL * DI + 255) / 256, 256>>>(delta, dt_proj_b + (size_t)L * DI);

        scan_kernel<<<(BB * DI * 2) / 128, 128>>>(
            xin, delta, xdbl, A_log + (size_t)L * DI * DS, D_param + (size_t)L * DI, y);

        gate_kernel<<<(BL * DI + 255) / 256, 256>>>(y, xr);
        launch_split(y, DI, BL, DI, Y_h, Y_l, BL, DI);

        // out_proj + residual: (2048x1536) @ (768x1536)^T, ADD into x
        gemm_mma<true><<<dim3(DM / 128, BL / 128), 256, SMEM>>>(
            Y_h, Y_l, Wout_h + (size_t)L * DM * DI, Wout_l + (size_t)L * DM * DI,
            x, DM, DM, DI);
    }

    rmsnorm_kernel<<<BL, 256>>>(x, norm_f_w, xn);
    launch_split(xn, DM, BL, DM, Xn_h, Xn_l, BL, DM);

    // lm_head: (2048x768) @ (32000x768)^T
    gemm_mma<false><<<dim3(VOC / 128, BL / 128), 256, SMEM>>>(
        Xn_h, Xn_l, Emb_h, Emb_l, out, VOC, VOC, DM);
}